// round 1
// baseline (speedup 1.0000x reference)
#include <cuda_runtime.h>
#include <cstdint>

// y[n,c,h,w] = x[n,c,h,w] * gamma[c] + beta[c]
// x: (8, 128, 256, 256) fp32. Inner spatial = 65536 elems = 16384 float4.
// In float4-index space: channel c = (i >> 14) & 127.

__global__ void scale_affine_kernel(const float4* __restrict__ x,
                                    const float* __restrict__ gamma,
                                    const float* __restrict__ beta,
                                    float4* __restrict__ y,
                                    long long n4) {
    long long i = (long long)blockIdx.x * blockDim.x + threadIdx.x;
    long long stride = (long long)gridDim.x * blockDim.x;

    #pragma unroll 4
    for (; i < n4; i += stride) {
        int c = (int)((i >> 14) & 127);
        float g = __ldg(&gamma[c]);
        float b = __ldg(&beta[c]);
        float4 v = x[i];
        v.x = fmaf(v.x, g, b);
        v.y = fmaf(v.y, g, b);
        v.z = fmaf(v.z, g, b);
        v.w = fmaf(v.w, g, b);
        y[i] = v;
    }
}

extern "C" void kernel_launch(void* const* d_in, const int* in_sizes, int n_in,
                              void* d_out, int out_size) {
    const float* x     = (const float*)d_in[0];
    const float* gamma = (const float*)d_in[1];
    const float* beta  = (const float*)d_in[2];
    float* out = (float*)d_out;

    long long n = (long long)out_size;       // 8*128*256*256 = 67,108,864
    long long n4 = n >> 2;                   // 16,777,216 float4

    const int threads = 256;
    // 148 SMs; aim for full occupancy with a handful of grid-stride iterations
    // each carrying unroll-4 independent LDG.128s for high MLP.
    int blocks = (int)((n4 + threads * 4 - 1) / (threads * 4));
    if (blocks > 148 * 32) blocks = 148 * 32;  // cap; grid-stride covers the rest

    scale_affine_kernel<<<blocks, threads>>>((const float4*)x, gamma, beta,
                                             (float4*)out, n4);
}